// round 3
// baseline (speedup 1.0000x reference)
#include <cuda_runtime.h>
#include <stdint.h>

#define CC   512
#define HWW  3136
#define WW   56
#define HH   56
#define NHEADS 16
#define DH   32
#define NB   8

// Scratch (allocation-free: static __device__ globals)
__device__ float g_q[(size_t)NB * NHEADS * HWW * DH];
__device__ float g_k[(size_t)NB * NHEADS * HWW * DH];
__device__ float g_v[(size_t)NB * NHEADS * HWW * DH];
__device__ float g_ao[(size_t)NB * HWW * CC];

// ---------------------------------------------------------------------------
// tf32 helpers
// ---------------------------------------------------------------------------
__device__ __forceinline__ float to_tf32(float x) {
    float y;
    asm("cvt.rna.tf32.f32 %0, %1;" : "=f"(y) : "f"(x));
    return y;
}
__device__ __forceinline__ float4 to_tf32_4(float4 v) {
    return make_float4(to_tf32(v.x), to_tf32(v.y), to_tf32(v.z), to_tf32(v.w));
}
__device__ __forceinline__ void mma_tf32(float c[4], uint32_t a0, uint32_t a1,
                                         uint32_t a2, uint32_t a3,
                                         uint32_t b0, uint32_t b1) {
    asm volatile(
        "mma.sync.aligned.m16n8k8.row.col.f32.tf32.tf32.f32 "
        "{%0,%1,%2,%3}, {%4,%5,%6,%7}, {%8,%9}, {%0,%1,%2,%3};\n"
        : "+f"(c[0]), "+f"(c[1]), "+f"(c[2]), "+f"(c[3])
        : "r"(a0), "r"(a1), "r"(a2), "r"(a3), "r"(b0), "r"(b1));
}

// ---------------------------------------------------------------------------
// Kernel 1: fused NHWC-gather + qkv GEMM (tf32 tensor cores). Unchanged.
// ---------------------------------------------------------------------------
__global__ __launch_bounds__(256, 2)
void qkv_gemm_tc(const float* __restrict__ x, const float* __restrict__ w)
{
    __shared__ float As[32 * 72];
    __shared__ float Bs[256 * 36];

    int m0 = blockIdx.x * 64;
    int n0 = blockIdx.y * 256;
    int b  = m0 / HWW;
    int pb0 = m0 % HWW;
    int t = threadIdx.x;
    int warp = t >> 5, lane = t & 31;
    int tg = lane & 3, g = lane >> 2;

    float c[4][4][4];
#pragma unroll
    for (int mt = 0; mt < 4; mt++)
#pragma unroll
        for (int nt = 0; nt < 4; nt++)
#pragma unroll
            for (int r = 0; r < 4; r++) c[mt][nt][r] = 0.f;

    const float* xb = x + (size_t)b * CC * HWW + pb0;

    for (int k0 = 0; k0 < CC; k0 += 32) {
        float4 av[2];
#pragma unroll
        for (int p = 0; p < 2; p++) {
            int kk = (t >> 4) + p * 16;
            int m4 = (t & 15) * 4;
            av[p] = *(const float4*)(xb + (size_t)(k0 + kk) * HWW + m4);
        }
        float4 bv[8];
#pragma unroll
        for (int i = 0; i < 8; i++) {
            int idx = t + 256 * i;
            int nn = idx >> 3;
            int k4 = (idx & 7) * 4;
            bv[i] = *(const float4*)(w + (size_t)(n0 + nn) * CC + k0 + k4);
        }
        __syncthreads();
#pragma unroll
        for (int p = 0; p < 2; p++) {
            int kk = (t >> 4) + p * 16;
            int m4 = (t & 15) * 4;
            *(float4*)&As[kk * 72 + m4] = to_tf32_4(av[p]);
        }
#pragma unroll
        for (int i = 0; i < 8; i++) {
            int idx = t + 256 * i;
            int nn = idx >> 3;
            int k4 = (idx & 7) * 4;
            *(float4*)&Bs[nn * 36 + k4] = to_tf32_4(bv[i]);
        }
        __syncthreads();
#pragma unroll
        for (int ks = 0; ks < 4; ks++) {
            int kb = ks * 8;
            uint32_t a[4][4];
#pragma unroll
            for (int mt = 0; mt < 4; mt++) {
                int mb = mt * 16 + g;
                a[mt][0] = __float_as_uint(As[(kb + tg) * 72 + mb]);
                a[mt][1] = __float_as_uint(As[(kb + tg) * 72 + mb + 8]);
                a[mt][2] = __float_as_uint(As[(kb + tg + 4) * 72 + mb]);
                a[mt][3] = __float_as_uint(As[(kb + tg + 4) * 72 + mb + 8]);
            }
            uint32_t bq[4][2];
#pragma unroll
            for (int nt = 0; nt < 4; nt++) {
                int nn = warp * 32 + nt * 8 + g;
                bq[nt][0] = __float_as_uint(Bs[nn * 36 + kb + tg]);
                bq[nt][1] = __float_as_uint(Bs[nn * 36 + kb + tg + 4]);
            }
#pragma unroll
            for (int mt = 0; mt < 4; mt++)
#pragma unroll
                for (int nt = 0; nt < 4; nt++)
                    mma_tf32(c[mt][nt], a[mt][0], a[mt][1], a[mt][2], a[mt][3],
                             bq[nt][0], bq[nt][1]);
        }
    }

    int nwb  = n0 + warp * 32;
    int sel  = nwb >> 9;
    int head = (nwb & 511) >> 5;
    float scl = (sel == 0) ? 0.17677669529663687f : 1.0f;
    float* dst = (sel == 0) ? g_q : (sel == 1) ? g_k : g_v;
    size_t plane = ((size_t)b * NHEADS + head) * HWW;
#pragma unroll
    for (int mt = 0; mt < 4; mt++) {
#pragma unroll
        for (int h = 0; h < 2; h++) {
            int hw = pb0 + mt * 16 + g + h * 8;
            float* row = dst + (plane + hw) * DH;
#pragma unroll
            for (int nt = 0; nt < 4; nt++) {
                int dd = nt * 8 + 2 * tg;
                float2 v2 = make_float2(c[mt][nt][h * 2] * scl,
                                        c[mt][nt][h * 2 + 1] * scl);
                *(float2*)(row + dd) = v2;
            }
        }
    }
}

// ---------------------------------------------------------------------------
// Kernel 2: neighborhood attention, two-phase.
//   QK phase: lane = neighbor (lane, lane+32); serial d-dot from smem.
//   Softmax in neighbor layout (2 butterflies, 2 exps per pixel-warp).
//   AV phase: lane = dim; weights via smem broadcast. 33-pad rows -> nearly
//   conflict-free for both phases.
// ---------------------------------------------------------------------------
__global__ __launch_bounds__(256)
void attn_kernel(const float* __restrict__ rpb)
{
    __shared__ float ks[140 * 33];
    __shared__ float vs[140 * 33];
    __shared__ float qs[32 * 32];
    __shared__ float rs[169];
    __shared__ float ws[32 * 52];

    int bh   = blockIdx.z;
    int head = bh & (NHEADS - 1);
    int bb   = bh >> 4;
    int i0   = blockIdx.y * 4;
    int j0   = blockIdx.x * 8;
    int rstart = max(0, min(i0 - 3, HH - 10));
    int cstart = max(0, min(j0 - 3, WW - 14));

    const float* kp = g_k + (size_t)bh * HWW * DH;
    const float* vp = g_v + (size_t)bh * HWW * DH;
    const float* qp = g_q + (size_t)bh * HWW * DH;

    // halo load (coalesced 128B rows; swizzle to 33-stride)
    for (int idx = threadIdx.x; idx < 140 * 32; idx += 256) {
        int r = idx >> 5, d = idx & 31;
        int hr = r / 14, hc = r - hr * 14;
        size_t gofs = ((size_t)(rstart + hr) * WW + cstart + hc) * DH + d;
        ks[r * 33 + d] = kp[gofs];
        vs[r * 33 + d] = vp[gofs];
    }
    for (int idx = threadIdx.x; idx < 32 * 32; idx += 256) {
        int p = idx >> 5, d = idx & 31;
        int qi = i0 + (p >> 3), qj = j0 + (p & 7);
        qs[idx] = qp[((size_t)qi * WW + qj) * DH + d];
    }
    if (threadIdx.x < 169) rs[threadIdx.x] = rpb[head * 169 + threadIdx.x];
    __syncthreads();

    int warp = threadIdx.x >> 5, lane = threadIdx.x & 31;
    int i  = i0 + (warp >> 1);
    int si = min(max(i - 3, 0), HH - 7);

    // per-lane neighbor decomposition (fixed across pixels)
    int a0 = lane / 7, c0 = lane - a0 * 7;
    int n1 = lane + 32;
    int a1 = n1 / 7, c1 = n1 - a1 * 7;
    bool l2 = lane < 17;
    if (!l2) { a1 = 0; c1 = 0; }
    int rofs0 = a0 * 14 + c0;
    int rofs1 = a1 * 14 + c1;

    for (int cc = 0; cc < 4; cc++) {
        int j  = j0 + (warp & 1) * 4 + cc;
        int sj = min(max(j - 3, 0), WW - 7);
        int pix = (warp >> 1) * 8 + (warp & 1) * 4 + cc;
        int nbase = (si - rstart) * 14 + (sj - cstart);

        const float* q   = &qs[pix * 32];
        const float* k0p = &ks[(nbase + rofs0) * 33];
        const float* k1p = &ks[(nbase + rofs1) * 33];
        float dot0 = 0.f, dot1 = 0.f;
#pragma unroll
        for (int d4 = 0; d4 < 8; d4++) {
            float4 qv = *(const float4*)(q + d4 * 4);
            dot0 = fmaf(qv.x, k0p[d4 * 4 + 0], dot0);
            dot1 = fmaf(qv.x, k1p[d4 * 4 + 0], dot1);
            dot0 = fmaf(qv.y, k0p[d4 * 4 + 1], dot0);
            dot1 = fmaf(qv.y, k1p[d4 * 4 + 1], dot1);
            dot0 = fmaf(qv.z, k0p[d4 * 4 + 2], dot0);
            dot1 = fmaf(qv.z, k1p[d4 * 4 + 2], dot1);
            dot0 = fmaf(qv.w, k0p[d4 * 4 + 3], dot0);
            dot1 = fmaf(qv.w, k1p[d4 * 4 + 3], dot1);
        }
        int bi = (si - i + 6) * 13 + (sj - j + 6);
        float lg0 = dot0 + rs[bi + a0 * 13 + c0];
        float lg1 = l2 ? (dot1 + rs[bi + a1 * 13 + c1]) : -1e30f;

        // softmax across 49 neighbors spread over lanes
        float m = fmaxf(lg0, lg1);
#pragma unroll
        for (int s = 16; s > 0; s >>= 1)
            m = fmaxf(m, __shfl_xor_sync(0xffffffffu, m, s));
        float e0 = __expf(lg0 - m);
        float e1 = l2 ? __expf(lg1 - m) : 0.f;
        float sum = e0 + e1;
#pragma unroll
        for (int s = 16; s > 0; s >>= 1)
            sum += __shfl_xor_sync(0xffffffffu, sum, s);
        float inv = 1.0f / sum;

        // stage unnormalized weights (within-warp handoff)
        ws[pix * 52 + lane] = e0;
        if (l2) ws[pix * 52 + 32 + lane] = e1;
        __syncwarp();

        // AV phase: lane = dim
        float acc = 0.f;
        const float* wp = &ws[pix * 52];
#pragma unroll
        for (int a = 0; a < 7; a++) {
            const float* vrow = &vs[((si + a - rstart) * 14 + (sj - cstart)) * 33 + lane];
#pragma unroll
            for (int c = 0; c < 7; c++)
                acc = fmaf(wp[a * 7 + c], vrow[c * 33], acc);
        }

        size_t pg = (size_t)bb * HWW + (size_t)i * WW + j;
        g_ao[pg * CC + head * DH + lane] = acc * inv;
    }
}

// ---------------------------------------------------------------------------
// Kernel 3: proj GEMM (tf32) + bias + NCHW transpose-store. Unchanged.
// ---------------------------------------------------------------------------
__global__ __launch_bounds__(256, 2)
void proj_gemm_tc(const float* __restrict__ w, const float* __restrict__ bias,
                  float* __restrict__ y)
{
    __shared__ float As[64 * 36];
    __shared__ float Bs[256 * 36];

    int m0 = blockIdx.x * 64;
    int n0 = blockIdx.y * 256;
    int b  = m0 / HWW;
    int pb0 = m0 % HWW;
    int t = threadIdx.x;
    int warp = t >> 5, lane = t & 31;
    int tg = lane & 3, g = lane >> 2;

    float c[4][4][4];
#pragma unroll
    for (int mt = 0; mt < 4; mt++)
#pragma unroll
        for (int nt = 0; nt < 4; nt++)
#pragma unroll
            for (int r = 0; r < 4; r++) c[mt][nt][r] = 0.f;

    const float* A = g_ao + (size_t)m0 * CC;

    for (int k0 = 0; k0 < CC; k0 += 32) {
        float4 av[2];
#pragma unroll
        for (int p = 0; p < 2; p++) {
            int idx = t + 256 * p;
            int mm = idx >> 3;
            int k4 = (idx & 7) * 4;
            av[p] = *(const float4*)(A + (size_t)mm * CC + k0 + k4);
        }
        float4 bv[8];
#pragma unroll
        for (int i = 0; i < 8; i++) {
            int idx = t + 256 * i;
            int nn = idx >> 3;
            int k4 = (idx & 7) * 4;
            bv[i] = *(const float4*)(w + (size_t)(n0 + nn) * CC + k0 + k4);
        }
        __syncthreads();
#pragma unroll
        for (int p = 0; p < 2; p++) {
            int idx = t + 256 * p;
            int mm = idx >> 3;
            int k4 = (idx & 7) * 4;
            *(float4*)&As[mm * 36 + k4] = to_tf32_4(av[p]);
        }
#pragma unroll
        for (int i = 0; i < 8; i++) {
            int idx = t + 256 * i;
            int nn = idx >> 3;
            int k4 = (idx & 7) * 4;
            *(float4*)&Bs[nn * 36 + k4] = to_tf32_4(bv[i]);
        }
        __syncthreads();
#pragma unroll
        for (int ks = 0; ks < 4; ks++) {
            int kb = ks * 8;
            uint32_t a[4][4];
#pragma unroll
            for (int mt = 0; mt < 4; mt++) {
                int mb = mt * 16 + g;
                a[mt][0] = __float_as_uint(As[mb * 36 + kb + tg]);
                a[mt][1] = __float_as_uint(As[(mb + 8) * 36 + kb + tg]);
                a[mt][2] = __float_as_uint(As[mb * 36 + kb + tg + 4]);
                a[mt][3] = __float_as_uint(As[(mb + 8) * 36 + kb + tg + 4]);
            }
            uint32_t bq[4][2];
#pragma unroll
            for (int nt = 0; nt < 4; nt++) {
                int nn = warp * 32 + nt * 8 + g;
                bq[nt][0] = __float_as_uint(Bs[nn * 36 + kb + tg]);
                bq[nt][1] = __float_as_uint(Bs[nn * 36 + kb + tg + 4]);
            }
#pragma unroll
            for (int mt = 0; mt < 4; mt++)
#pragma unroll
                for (int nt = 0; nt < 4; nt++)
                    mma_tf32(c[mt][nt], a[mt][0], a[mt][1], a[mt][2], a[mt][3],
                             bq[nt][0], bq[nt][1]);
        }
    }

#pragma unroll
    for (int nt = 0; nt < 4; nt++) {
        int n = n0 + warp * 32 + nt * 8 + 2 * tg;
        float bv0 = bias[n];
        float bv1 = bias[n + 1];
        float* y0 = y + ((size_t)b * CC + n) * HWW;
        float* y1 = y0 + HWW;
#pragma unroll
        for (int mt = 0; mt < 4; mt++) {
#pragma unroll
            for (int h = 0; h < 2; h++) {
                int hw = pb0 + mt * 16 + g + h * 8;
                y0[hw] = c[mt][nt][h * 2]     + bv0;
                y1[hw] = c[mt][nt][h * 2 + 1] + bv1;
            }
        }
    }
}

// ---------------------------------------------------------------------------
extern "C" void kernel_launch(void* const* d_in, const int* in_sizes, int n_in,
                              void* d_out, int out_size)
{
    const float* x      = (const float*)d_in[0];
    const float* qkv_w  = (const float*)d_in[1];
    const float* rpb    = (const float*)d_in[2];
    const float* proj_w = (const float*)d_in[3];
    const float* proj_b = (const float*)d_in[4];
    float* y = (float*)d_out;

    qkv_gemm_tc<<<dim3(392, 6), 256>>>(x, qkv_w);
    attn_kernel<<<dim3(7, 14, NB * NHEADS), 256>>>(rpb);
    proj_gemm_tc<<<dim3(392, 2), 256>>>(proj_w, proj_b, y);
}

// round 5
// speedup vs baseline: 1.3986x; 1.3986x over previous
#include <cuda_runtime.h>
#include <stdint.h>

#define CC   512
#define HWW  3136
#define WW   56
#define HH   56
#define NHEADS 16
#define DH   32
#define NB   8

// Scratch (allocation-free: static __device__ globals)
__device__ float g_q[(size_t)NB * NHEADS * HWW * DH];
__device__ float g_k[(size_t)NB * NHEADS * HWW * DH];
__device__ float g_v[(size_t)NB * NHEADS * HWW * DH];
__device__ float g_ao[(size_t)NB * HWW * CC];

// ---------------------------------------------------------------------------
// tf32 helpers
// ---------------------------------------------------------------------------
__device__ __forceinline__ float to_tf32(float x) {
    float y;
    asm("cvt.rna.tf32.f32 %0, %1;" : "=f"(y) : "f"(x));
    return y;
}
__device__ __forceinline__ float4 to_tf32_4(float4 v) {
    return make_float4(to_tf32(v.x), to_tf32(v.y), to_tf32(v.z), to_tf32(v.w));
}
__device__ __forceinline__ void mma_tf32(float c[4], uint32_t a0, uint32_t a1,
                                         uint32_t a2, uint32_t a3,
                                         uint32_t b0, uint32_t b1) {
    asm volatile(
        "mma.sync.aligned.m16n8k8.row.col.f32.tf32.tf32.f32 "
        "{%0,%1,%2,%3}, {%4,%5,%6,%7}, {%8,%9}, {%0,%1,%2,%3};\n"
        : "+f"(c[0]), "+f"(c[1]), "+f"(c[2]), "+f"(c[3])
        : "r"(a0), "r"(a1), "r"(a2), "r"(a3), "r"(b0), "r"(b1));
}

// Dynamic-smem double buffer layout (both GEMMs):
//   buffer b at float offset b*6912;  As = +0 (2304 floats), Bs = +2304 (4608)
#define SBUF 6912
#define SMEM_GEMM_BYTES (2 * SBUF * 4)

// ---------------------------------------------------------------------------
// Kernel 1: fused NHWC-gather + qkv GEMM (tf32, double-buffered pipeline).
// BM=64, BN=128, BK=32. 8 warps, warp tile 64m x 16n (4mt x 2nt m16n8k8).
// As: [k][m] stride 72; Bs: [n][k] stride 36. One __syncthreads per k-iter;
// next tile's LDGs issue before the MMA section.
// ---------------------------------------------------------------------------
__global__ __launch_bounds__(256, 2)
void qkv_gemm_tc(const float* __restrict__ x, const float* __restrict__ w)
{
    extern __shared__ float dsm[];

    int m0 = blockIdx.x * 64;
    int n0 = blockIdx.y * 128;
    int b  = m0 / HWW;
    int pb0 = m0 % HWW;
    int t = threadIdx.x;
    int warp = t >> 5, lane = t & 31;
    int tg = lane & 3, g = lane >> 2;

    float c[4][2][4];
#pragma unroll
    for (int mt = 0; mt < 4; mt++)
#pragma unroll
        for (int nt = 0; nt < 2; nt++)
#pragma unroll
            for (int r = 0; r < 4; r++) c[mt][nt][r] = 0.f;

    const float* xb = x + (size_t)b * CC * HWW + pb0;

    int a_kk = t >> 4;            // + p*16
    int a_m4 = (t & 15) * 4;
    float4 av[2], bv[4];

    // ---- prologue: tile 0 ----
#pragma unroll
    for (int p = 0; p < 2; p++)
        av[p] = *(const float4*)(xb + (size_t)(a_kk + p * 16) * HWW + a_m4);
#pragma unroll
    for (int i = 0; i < 4; i++) {
        int idx = t + 256 * i;
        int nn = idx >> 3, k4 = (idx & 7) * 4;
        bv[i] = *(const float4*)(w + (size_t)(n0 + nn) * CC + k4);
    }
    {
        float* As = dsm;
        float* Bs = dsm + 2304;
#pragma unroll
        for (int p = 0; p < 2; p++)
            *(float4*)&As[(a_kk + p * 16) * 72 + a_m4] = to_tf32_4(av[p]);
#pragma unroll
        for (int i = 0; i < 4; i++) {
            int idx = t + 256 * i;
            int nn = idx >> 3, k4 = (idx & 7) * 4;
            *(float4*)&Bs[nn * 36 + k4] = to_tf32_4(bv[i]);
        }
    }
    __syncthreads();

    for (int it = 0; it < 16; it++) {
        float* As = dsm + (it & 1) * SBUF;
        float* Bs = As + 2304;

        if (it < 15) {
            int k0 = (it + 1) * 32;
#pragma unroll
            for (int p = 0; p < 2; p++)
                av[p] = *(const float4*)(xb + (size_t)(k0 + a_kk + p * 16) * HWW + a_m4);
#pragma unroll
            for (int i = 0; i < 4; i++) {
                int idx = t + 256 * i;
                int nn = idx >> 3, k4 = (idx & 7) * 4;
                bv[i] = *(const float4*)(w + (size_t)(n0 + nn) * CC + k0 + k4);
            }
        }

        // ---- MMA on current buffer (overlaps in-flight LDGs) ----
#pragma unroll
        for (int ks = 0; ks < 4; ks++) {
            int kb = ks * 8;
            uint32_t a[4][4];
#pragma unroll
            for (int mt = 0; mt < 4; mt++) {
                int mb = mt * 16 + g;
                a[mt][0] = __float_as_uint(As[(kb + tg) * 72 + mb]);
                a[mt][1] = __float_as_uint(As[(kb + tg) * 72 + mb + 8]);
                a[mt][2] = __float_as_uint(As[(kb + tg + 4) * 72 + mb]);
                a[mt][3] = __float_as_uint(As[(kb + tg + 4) * 72 + mb + 8]);
            }
            uint32_t bq[2][2];
#pragma unroll
            for (int nt = 0; nt < 2; nt++) {
                int nn = warp * 16 + nt * 8 + g;
                bq[nt][0] = __float_as_uint(Bs[nn * 36 + kb + tg]);
                bq[nt][1] = __float_as_uint(Bs[nn * 36 + kb + tg + 4]);
            }
#pragma unroll
            for (int mt = 0; mt < 4; mt++)
#pragma unroll
                for (int nt = 0; nt < 2; nt++)
                    mma_tf32(c[mt][nt], a[mt][0], a[mt][1], a[mt][2], a[mt][3],
                             bq[nt][0], bq[nt][1]);
        }

        if (it < 15) {
            float* Asn = dsm + ((it + 1) & 1) * SBUF;
            float* Bsn = Asn + 2304;
#pragma unroll
            for (int p = 0; p < 2; p++)
                *(float4*)&Asn[(a_kk + p * 16) * 72 + a_m4] = to_tf32_4(av[p]);
#pragma unroll
            for (int i = 0; i < 4; i++) {
                int idx = t + 256 * i;
                int nn = idx >> 3, k4 = (idx & 7) * 4;
                *(float4*)&Bsn[nn * 36 + k4] = to_tf32_4(bv[i]);
            }
        }
        __syncthreads();
    }

    // ---- epilogue: warp covers 16 n = half of one head's 32 dims ----
    int nwb  = n0 + warp * 16;
    int sel  = nwb >> 9;
    int head = (nwb & 511) >> 5;
    int dbase = nwb & 31;          // 0 or 16
    float scl = (sel == 0) ? 0.17677669529663687f : 1.0f;
    float* dst = (sel == 0) ? g_q : (sel == 1) ? g_k : g_v;
    size_t plane = ((size_t)b * NHEADS + head) * HWW;
#pragma unroll
    for (int mt = 0; mt < 4; mt++) {
#pragma unroll
        for (int h = 0; h < 2; h++) {
            int hw = pb0 + mt * 16 + g + h * 8;
            float* row = dst + (plane + hw) * DH;
#pragma unroll
            for (int nt = 0; nt < 2; nt++) {
                int dd = dbase + nt * 8 + 2 * tg;
                float2 v2 = make_float2(c[mt][nt][h * 2] * scl,
                                        c[mt][nt][h * 2 + 1] * scl);
                *(float2*)(row + dd) = v2;
            }
        }
    }
}

// ---------------------------------------------------------------------------
// Kernel 2: neighborhood attention, two-phase, vectorized QK.
//   All shared arrays are 16B-aligned (pw/ks are read as float4 — the R4
//   crash was pw landing at base%16==4 behind the odd-sized rs array).
// ---------------------------------------------------------------------------
__global__ __launch_bounds__(256)
void attn_kernel(const float* __restrict__ rpb)
{
    __shared__ __align__(16) float ks[140 * 36];
    __shared__ __align__(16) float vs[140 * 33];
    __shared__ __align__(16) float pw[32 * 52];
    __shared__ __align__(16) float rs[169];

    int bh   = blockIdx.z;
    int head = bh & (NHEADS - 1);
    int bb   = bh >> 4;
    int i0   = blockIdx.y * 4;
    int j0   = blockIdx.x * 8;
    int rstart = max(0, min(i0 - 3, HH - 10));
    int cstart = max(0, min(j0 - 3, WW - 14));

    const float* kp = g_k + (size_t)bh * HWW * DH;
    const float* vp = g_v + (size_t)bh * HWW * DH;
    const float* qp = g_q + (size_t)bh * HWW * DH;

    for (int idx = threadIdx.x; idx < 140 * 32; idx += 256) {
        int r = idx >> 5, d = idx & 31;
        int hr = r / 14, hc = r - hr * 14;
        size_t gofs = ((size_t)(rstart + hr) * WW + cstart + hc) * DH + d;
        ks[r * 36 + d] = kp[gofs];
        vs[r * 33 + d] = vp[gofs];
    }
    for (int idx = threadIdx.x; idx < 32 * 32; idx += 256) {
        int p = idx >> 5, d = idx & 31;
        int qi = i0 + (p >> 3), qj = j0 + (p & 7);
        pw[p * 52 + d] = qp[((size_t)qi * WW + qj) * DH + d];
    }
    if (threadIdx.x < 169) rs[threadIdx.x] = rpb[head * 169 + threadIdx.x];
    __syncthreads();

    int warp = threadIdx.x >> 5, lane = threadIdx.x & 31;
    int i  = i0 + (warp >> 1);
    int si = min(max(i - 3, 0), HH - 7);

    // per-lane neighbor decomposition (fixed across pixels)
    int a0 = lane / 7, c0 = lane - a0 * 7;
    int n1 = lane + 32;
    int a1 = n1 / 7, c1 = n1 - a1 * 7;
    bool l2 = lane < 17;
    if (!l2) { a1 = 0; c1 = 0; }
    int rofs0 = a0 * 14 + c0;
    int rofs1 = a1 * 14 + c1;

    for (int cc = 0; cc < 4; cc++) {
        int j  = j0 + (warp & 1) * 4 + cc;
        int sj = min(max(j - 3, 0), WW - 7);
        int pix = (warp >> 1) * 8 + (warp & 1) * 4 + cc;
        int nbase = (si - rstart) * 14 + (sj - cstart);

        const float* q   = &pw[pix * 52];
        const float* k0p = &ks[(nbase + rofs0) * 36];
        const float* k1p = &ks[(nbase + rofs1) * 36];
        float dot0 = 0.f, dot1 = 0.f;
#pragma unroll
        for (int d4 = 0; d4 < 8; d4++) {
            float4 qv  = *(const float4*)(q   + d4 * 4);
            float4 k0v = *(const float4*)(k0p + d4 * 4);
            float4 k1v = *(const float4*)(k1p + d4 * 4);
            dot0 = fmaf(qv.x, k0v.x, dot0);
            dot1 = fmaf(qv.x, k1v.x, dot1);
            dot0 = fmaf(qv.y, k0v.y, dot0);
            dot1 = fmaf(qv.y, k1v.y, dot1);
            dot0 = fmaf(qv.z, k0v.z, dot0);
            dot1 = fmaf(qv.z, k1v.z, dot1);
            dot0 = fmaf(qv.w, k0v.w, dot0);
            dot1 = fmaf(qv.w, k1v.w, dot1);
        }
        int bi = (si - i + 6) * 13 + (sj - j + 6);
        float lg0 = dot0 + rs[bi + a0 * 13 + c0];
        float lg1 = l2 ? (dot1 + rs[bi + a1 * 13 + c1]) : -1e30f;

        // softmax across 49 neighbors spread over lanes
        float m = fmaxf(lg0, lg1);
#pragma unroll
        for (int s = 16; s > 0; s >>= 1)
            m = fmaxf(m, __shfl_xor_sync(0xffffffffu, m, s));
        float e0 = __expf(lg0 - m);
        float e1 = l2 ? __expf(lg1 - m) : 0.f;
        float sum = e0 + e1;
#pragma unroll
        for (int s = 16; s > 0; s >>= 1)
            sum += __shfl_xor_sync(0xffffffffu, sum, s);
        float inv = 1.0f / sum;

        // stage unnormalized weights into the (now dead) q slot
        float* wslot = &pw[pix * 52];
        wslot[lane] = e0;
        if (l2) wslot[32 + lane] = e1;
        __syncwarp();

        // AV phase: lane = dim
        float acc = 0.f;
#pragma unroll
        for (int a = 0; a < 7; a++) {
            const float* vrow = &vs[((si + a - rstart) * 14 + (sj - cstart)) * 33 + lane];
#pragma unroll
            for (int c = 0; c < 7; c++)
                acc = fmaf(wslot[a * 7 + c], vrow[c * 33], acc);
        }
        __syncwarp();   // protect wslot until all lanes consumed it

        size_t pg = (size_t)bb * HWW + (size_t)i * WW + j;
        g_ao[pg * CC + head * DH + lane] = acc * inv;
    }
}

// ---------------------------------------------------------------------------
// Kernel 3: proj GEMM (tf32, double-buffered) + bias + NCHW transpose-store.
// BM=64, BN=128, BK=32. As: [m][k] stride 36; Bs: [n][k] stride 36.
// ---------------------------------------------------------------------------
__global__ __launch_bounds__(256, 2)
void proj_gemm_tc(const float* __restrict__ w, const float* __restrict__ bias,
                  float* __restrict__ y)
{
    extern __shared__ float dsm[];

    int m0 = blockIdx.x * 64;
    int n0 = blockIdx.y * 128;
    int b  = m0 / HWW;
    int pb0 = m0 % HWW;
    int t = threadIdx.x;
    int warp = t >> 5, lane = t & 31;
    int tg = lane & 3, g = lane >> 2;

    float c[4][2][4];
#pragma unroll
    for (int mt = 0; mt < 4; mt++)
#pragma unroll
        for (int nt = 0; nt < 2; nt++)
#pragma unroll
            for (int r = 0; r < 4; r++) c[mt][nt][r] = 0.f;

    const float* A = g_ao + (size_t)m0 * CC;
    float4 av[2], bv[4];

    // prologue
#pragma unroll
    for (int p = 0; p < 2; p++) {
        int idx = t + 256 * p;
        int mm = idx >> 3, k4 = (idx & 7) * 4;
        av[p] = *(const float4*)(A + (size_t)mm * CC + k4);
    }
#pragma unroll
    for (int i = 0; i < 4; i++) {
        int idx = t + 256 * i;
        int nn = idx >> 3, k4 = (idx & 7) * 4;
        bv[i] = *(const float4*)(w + (size_t)(n0 + nn) * CC + k4);
    }
    {
        float* As = dsm;
        float* Bs = dsm + 2304;
#pragma unroll
        for (int p = 0; p < 2; p++) {
            int idx = t + 256 * p;
            int mm = idx >> 3, k4 = (idx & 7) * 4;
            *(float4*)&As[mm * 36 + k4] = to_tf32_4(av[p]);
        }
#pragma unroll
        for (int i = 0; i < 4; i++) {
            int idx = t + 256 * i;
            int nn = idx >> 3, k4 = (idx & 7) * 4;
            *(float4*)&Bs[nn * 36 + k4] = to_tf32_4(bv[i]);
        }
    }
    __syncthreads();

    for (int it = 0; it < 16; it++) {
        float* As = dsm + (it & 1) * SBUF;
        float* Bs = As + 2304;

        if (it < 15) {
            int k0 = (it + 1) * 32;
#pragma unroll
            for (int p = 0; p < 2; p++) {
                int idx = t + 256 * p;
                int mm = idx >> 3, k4 = (idx & 7) * 4;
                av[p] = *(const float4*)(A + (size_t)mm * CC + k0 + k4);
            }
#pragma unroll
            for (int i = 0; i < 4; i++) {
                int idx = t + 256 * i;
                int nn = idx >> 3, k4 = (idx & 7) * 4;
                bv[i] = *(const float4*)(w + (size_t)(n0 + nn) * CC + k0 + k4);
            }
        }

#pragma unroll
        for (int ks = 0; ks < 4; ks++) {
            int kb = ks * 8;
            uint32_t a[4][4];
#pragma unroll
            for (int mt = 0; mt < 4; mt++) {
                int mb = mt * 16 + g;
                a[mt][0] = __float_as_uint(As[mb * 36 + kb + tg]);
                a[mt][1] = __float_as_uint(As[(mb + 8) * 36 + kb + tg]);
                a[mt][2] = __float_as_uint(As[mb * 36 + kb + tg + 4]);
                a[mt][3] = __float_as_uint(As[(mb + 8) * 36 + kb + tg + 4]);
            }
            uint32_t bq[2][2];
#pragma unroll
            for (int nt = 0; nt < 2; nt++) {
                int nn = warp * 16 + nt * 8 + g;
                bq[nt][0] = __float_as_uint(Bs[nn * 36 + kb + tg]);
                bq[nt][1] = __float_as_uint(Bs[nn * 36 + kb + tg + 4]);
            }
#pragma unroll
            for (int mt = 0; mt < 4; mt++)
#pragma unroll
                for (int nt = 0; nt < 2; nt++)
                    mma_tf32(c[mt][nt], a[mt][0], a[mt][1], a[mt][2], a[mt][3],
                             bq[nt][0], bq[nt][1]);
        }

        if (it < 15) {
            float* Asn = dsm + ((it + 1) & 1) * SBUF;
            float* Bsn = Asn + 2304;
#pragma unroll
            for (int p = 0; p < 2; p++) {
                int idx = t + 256 * p;
                int mm = idx >> 3, k4 = (idx & 7) * 4;
                *(float4*)&Asn[mm * 36 + k4] = to_tf32_4(av[p]);
            }
#pragma unroll
            for (int i = 0; i < 4; i++) {
                int idx = t + 256 * i;
                int nn = idx >> 3, k4 = (idx & 7) * 4;
                *(float4*)&Bsn[nn * 36 + k4] = to_tf32_4(bv[i]);
            }
        }
        __syncthreads();
    }

    // ---- epilogue: NCHW store with bias ----
#pragma unroll
    for (int nt = 0; nt < 2; nt++) {
        int n = n0 + warp * 16 + nt * 8 + 2 * tg;
        float bv0 = bias[n];
        float bv1 = bias[n + 1];
        float* y0 = y + ((size_t)b * CC + n) * HWW;
        float* y1 = y0 + HWW;
#pragma unroll
        for (int mt = 0; mt < 4; mt++) {
#pragma unroll
            for (int h = 0; h < 2; h++) {
                int hw = pb0 + mt * 16 + g + h * 8;
                y0[hw] = c[mt][nt][h * 2]     + bv0;
                y1[hw] = c[mt][nt][h * 2 + 1] + bv1;
            }
        }
    }
}

// ---------------------------------------------------------------------------
extern "C" void kernel_launch(void* const* d_in, const int* in_sizes, int n_in,
                              void* d_out, int out_size)
{
    const float* x      = (const float*)d_in[0];
    const float* qkv_w  = (const float*)d_in[1];
    const float* rpb    = (const float*)d_in[2];
    const float* proj_w = (const float*)d_in[3];
    const float* proj_b = (const float*)d_in[4];
    float* y = (float*)d_out;

    // 54 KB dynamic smem (> 48 KB default) — config call, not an allocation.
    cudaFuncSetAttribute(qkv_gemm_tc,
        cudaFuncAttributeMaxDynamicSharedMemorySize, SMEM_GEMM_BYTES);
    cudaFuncSetAttribute(proj_gemm_tc,
        cudaFuncAttributeMaxDynamicSharedMemorySize, SMEM_GEMM_BYTES);

    qkv_gemm_tc<<<dim3(392, 12), 256, SMEM_GEMM_BYTES>>>(x, qkv_w);
    attn_kernel<<<dim3(7, 14, NB * NHEADS), 256>>>(rpb);
    proj_gemm_tc<<<dim3(392, 4), 256, SMEM_GEMM_BYTES>>>(proj_w, proj_b, y);
}

// round 9
// speedup vs baseline: 1.5819x; 1.1311x over previous
#include <cuda_runtime.h>
#include <stdint.h>

#define CC   512
#define HWW  3136
#define WW   56
#define HH   56
#define NHEADS 16
#define DH   32
#define NB   8

#define XT_N ((size_t)NB * CC * HWW)      // 12,845,056
#define WQ_N ((size_t)3 * CC * CC)        // 786,432
#define WP_N ((size_t)CC * CC)            // 262,144

// Scratch (allocation-free: static __device__ globals)
__device__ float g_q[(size_t)NB * NHEADS * HWW * DH];
__device__ float g_k[(size_t)NB * NHEADS * HWW * DH];
__device__ float g_v[(size_t)NB * NHEADS * HWW * DH];
__device__ float g_ao[(size_t)NB * HWW * CC];
__device__ float g_xt[XT_N];     // tf32-rounded x
__device__ float g_wq[WQ_N];     // tf32-rounded qkv_w
__device__ float g_wp[WP_N];     // tf32-rounded proj_w

// ---------------------------------------------------------------------------
// tf32 / cp.async helpers
// ---------------------------------------------------------------------------
__device__ __forceinline__ float to_tf32(float x) {
    float y;
    asm("cvt.rna.tf32.f32 %0, %1;" : "=f"(y) : "f"(x));
    return y;
}
__device__ __forceinline__ float4 to_tf32_4(float4 v) {
    return make_float4(to_tf32(v.x), to_tf32(v.y), to_tf32(v.z), to_tf32(v.w));
}
__device__ __forceinline__ void mma_tf32(float c[4], uint32_t a0, uint32_t a1,
                                         uint32_t a2, uint32_t a3,
                                         uint32_t b0, uint32_t b1) {
    asm volatile(
        "mma.sync.aligned.m16n8k8.row.col.f32.tf32.tf32.f32 "
        "{%0,%1,%2,%3}, {%4,%5,%6,%7}, {%8,%9}, {%0,%1,%2,%3};\n"
        : "+f"(c[0]), "+f"(c[1]), "+f"(c[2]), "+f"(c[3])
        : "r"(a0), "r"(a1), "r"(a2), "r"(a3), "r"(b0), "r"(b1));
}
__device__ __forceinline__ void cp_async16(float* smem_dst, const float* gsrc) {
    uint32_t s = (uint32_t)__cvta_generic_to_shared(smem_dst);
    asm volatile("cp.async.cg.shared.global [%0], [%1], 16;\n" :: "r"(s), "l"(gsrc));
}
#define CP_COMMIT() asm volatile("cp.async.commit_group;\n" ::: "memory")
#define CP_WAIT0()  asm volatile("cp.async.wait_group 0;\n" ::: "memory")

// Per-buffer float counts (identical for both GEMMs):
//   As = 2304 floats (qkv: [32k][72m-pad]; proj: [64m][36k-pad]), Bs = 9216.
#define SBUF 11520
#define SMEM_GEMM_BYTES (2 * SBUF * 4)   // 92160 B

// ---------------------------------------------------------------------------
// Kernel 0: tf32 pre-rounding of x, qkv_w, proj_w (float4 grid-stride).
// ---------------------------------------------------------------------------
__global__ void prep_round(const float* __restrict__ x,
                           const float* __restrict__ wq,
                           const float* __restrict__ wp)
{
    size_t i0 = (size_t)blockIdx.x * 256 + threadIdx.x;
    size_t stride = (size_t)gridDim.x * 256;
    for (size_t i = i0; i < XT_N / 4; i += stride)
        ((float4*)g_xt)[i] = to_tf32_4(((const float4*)x)[i]);
    for (size_t i = i0; i < WQ_N / 4; i += stride)
        ((float4*)g_wq)[i] = to_tf32_4(((const float4*)wq)[i]);
    for (size_t i = i0; i < WP_N / 4; i += stride)
        ((float4*)g_wp)[i] = to_tf32_4(((const float4*)wp)[i]);
}

// ---------------------------------------------------------------------------
// Kernel 1: qkv GEMM (tf32, cp.async double-buffered).
// Reads g_xt / g_wq via device-side symbol reference (NOT host-passed args —
// that was the R6 rel_err=1.0 bug: host address of a __device__ symbol is
// garbage without cudaGetSymbolAddress).
// BM=64, BN=256, BK=32. 8 warps, warp tile 64m x 32n (4mt x 4nt m16n8k8).
// As: [k][m] stride 72; Bs: [n][k] stride 36. Inputs pre-rounded to tf32.
// ---------------------------------------------------------------------------
__global__ __launch_bounds__(256, 2)
void qkv_gemm_tc()
{
    extern __shared__ float dsm[];
    const float* __restrict__ x = g_xt;
    const float* __restrict__ w = g_wq;

    int m0 = blockIdx.x * 64;
    int n0 = blockIdx.y * 256;
    int b  = m0 / HWW;
    int pb0 = m0 % HWW;
    int t = threadIdx.x;
    int warp = t >> 5, lane = t & 31;
    int tg = lane & 3, g = lane >> 2;

    float c[4][4][4];
#pragma unroll
    for (int mt = 0; mt < 4; mt++)
#pragma unroll
        for (int nt = 0; nt < 4; nt++)
#pragma unroll
            for (int r = 0; r < 4; r++) c[mt][nt][r] = 0.f;

    const float* xb = x + (size_t)b * CC * HWW + pb0;
    int a_kk = t >> 4;            // + p*16
    int a_m4 = (t & 15) * 4;

    // tile issue: A = 2 chunks, B = 8 chunks per thread
    auto issue_tile = [&](int k0, float* buf) {
        float* As = buf;
        float* Bs = buf + 2304;
#pragma unroll
        for (int p = 0; p < 2; p++)
            cp_async16(&As[(a_kk + p * 16) * 72 + a_m4],
                       xb + (size_t)(k0 + a_kk + p * 16) * HWW + a_m4);
#pragma unroll
        for (int i = 0; i < 8; i++) {
            int idx = t + 256 * i;
            int nn = idx >> 3, k4 = (idx & 7) * 4;
            cp_async16(&Bs[nn * 36 + k4],
                       w + (size_t)(n0 + nn) * CC + k0 + k4);
        }
    };

    issue_tile(0, dsm);
    CP_COMMIT();

    for (int it = 0; it < 16; it++) {
        float* As = dsm + (it & 1) * SBUF;
        float* Bs = As + 2304;

        CP_WAIT0();
        __syncthreads();
        if (it < 15) {
            issue_tile((it + 1) * 32, dsm + ((it + 1) & 1) * SBUF);
            CP_COMMIT();
        }

#pragma unroll
        for (int ks = 0; ks < 4; ks++) {
            int kb = ks * 8;
            uint32_t a[4][4];
#pragma unroll
            for (int mt = 0; mt < 4; mt++) {
                int mb = mt * 16 + g;
                a[mt][0] = __float_as_uint(As[(kb + tg) * 72 + mb]);
                a[mt][1] = __float_as_uint(As[(kb + tg) * 72 + mb + 8]);
                a[mt][2] = __float_as_uint(As[(kb + tg + 4) * 72 + mb]);
                a[mt][3] = __float_as_uint(As[(kb + tg + 4) * 72 + mb + 8]);
            }
            uint32_t bq[4][2];
#pragma unroll
            for (int nt = 0; nt < 4; nt++) {
                int nn = warp * 32 + nt * 8 + g;
                bq[nt][0] = __float_as_uint(Bs[nn * 36 + kb + tg]);
                bq[nt][1] = __float_as_uint(Bs[nn * 36 + kb + tg + 4]);
            }
#pragma unroll
            for (int mt = 0; mt < 4; mt++)
#pragma unroll
                for (int nt = 0; nt < 4; nt++)
                    mma_tf32(c[mt][nt], a[mt][0], a[mt][1], a[mt][2], a[mt][3],
                             bq[nt][0], bq[nt][1]);
        }
        __syncthreads();
    }

    // ---- epilogue: warp covers exactly 32 n = one (sel, head) ----
    int nwb  = n0 + warp * 32;
    int sel  = nwb >> 9;
    int head = (nwb & 511) >> 5;
    float scl = (sel == 0) ? 0.17677669529663687f : 1.0f;
    float* dst = (sel == 0) ? g_q : (sel == 1) ? g_k : g_v;
    size_t plane = ((size_t)b * NHEADS + head) * HWW;
#pragma unroll
    for (int mt = 0; mt < 4; mt++) {
#pragma unroll
        for (int h = 0; h < 2; h++) {
            int hw = pb0 + mt * 16 + g + h * 8;
            float* row = dst + (plane + hw) * DH;
#pragma unroll
            for (int nt = 0; nt < 4; nt++) {
                int dd = nt * 8 + 2 * tg;
                float2 v2 = make_float2(c[mt][nt][h * 2] * scl,
                                        c[mt][nt][h * 2 + 1] * scl);
                *(float2*)(row + dd) = v2;
            }
        }
    }
}

// ---------------------------------------------------------------------------
// Kernel 2: neighborhood attention, two-phase, vectorized QK.
// Output written tf32-rounded so proj can consume it via cp.async.
// ---------------------------------------------------------------------------
__global__ __launch_bounds__(256)
void attn_kernel(const float* __restrict__ rpb)
{
    __shared__ __align__(16) float ks[140 * 36];
    __shared__ __align__(16) float vs[140 * 33];
    __shared__ __align__(16) float pw[32 * 52];
    __shared__ __align__(16) float rs[169];

    int bh   = blockIdx.z;
    int head = bh & (NHEADS - 1);
    int bb   = bh >> 4;
    int i0   = blockIdx.y * 4;
    int j0   = blockIdx.x * 8;
    int rstart = max(0, min(i0 - 3, HH - 10));
    int cstart = max(0, min(j0 - 3, WW - 14));

    const float* kp = g_k + (size_t)bh * HWW * DH;
    const float* vp = g_v + (size_t)bh * HWW * DH;
    const float* qp = g_q + (size_t)bh * HWW * DH;

    for (int idx = threadIdx.x; idx < 140 * 32; idx += 256) {
        int r = idx >> 5, d = idx & 31;
        int hr = r / 14, hc = r - hr * 14;
        size_t gofs = ((size_t)(rstart + hr) * WW + cstart + hc) * DH + d;
        ks[r * 36 + d] = kp[gofs];
        vs[r * 33 + d] = vp[gofs];
    }
    for (int idx = threadIdx.x; idx < 32 * 32; idx += 256) {
        int p = idx >> 5, d = idx & 31;
        int qi = i0 + (p >> 3), qj = j0 + (p & 7);
        pw[p * 52 + d] = qp[((size_t)qi * WW + qj) * DH + d];
    }
    if (threadIdx.x < 169) rs[threadIdx.x] = rpb[head * 169 + threadIdx.x];
    __syncthreads();

    int warp = threadIdx.x >> 5, lane = threadIdx.x & 31;
    int i  = i0 + (warp >> 1);
    int si = min(max(i - 3, 0), HH - 7);

    int a0 = lane / 7, c0 = lane - a0 * 7;
    int n1 = lane + 32;
    int a1 = n1 / 7, c1 = n1 - a1 * 7;
    bool l2 = lane < 17;
    if (!l2) { a1 = 0; c1 = 0; }
    int rofs0 = a0 * 14 + c0;
    int rofs1 = a1 * 14 + c1;

    for (int cc = 0; cc < 4; cc++) {
        int j  = j0 + (warp & 1) * 4 + cc;
        int sj = min(max(j - 3, 0), WW - 7);
        int pix = (warp >> 1) * 8 + (warp & 1) * 4 + cc;
        int nbase = (si - rstart) * 14 + (sj - cstart);

        const float* q   = &pw[pix * 52];
        const float* k0p = &ks[(nbase + rofs0) * 36];
        const float* k1p = &ks[(nbase + rofs1) * 36];
        float dot0 = 0.f, dot1 = 0.f;
#pragma unroll
        for (int d4 = 0; d4 < 8; d4++) {
            float4 qv  = *(const float4*)(q   + d4 * 4);
            float4 k0v = *(const float4*)(k0p + d4 * 4);
            float4 k1v = *(const float4*)(k1p + d4 * 4);
            dot0 = fmaf(qv.x, k0v.x, dot0);
            dot1 = fmaf(qv.x, k1v.x, dot1);
            dot0 = fmaf(qv.y, k0v.y, dot0);
            dot1 = fmaf(qv.y, k1v.y, dot1);
            dot0 = fmaf(qv.z, k0v.z, dot0);
            dot1 = fmaf(qv.z, k1v.z, dot1);
            dot0 = fmaf(qv.w, k0v.w, dot0);
            dot1 = fmaf(qv.w, k1v.w, dot1);
        }
        int bi = (si - i + 6) * 13 + (sj - j + 6);
        float lg0 = dot0 + rs[bi + a0 * 13 + c0];
        float lg1 = l2 ? (dot1 + rs[bi + a1 * 13 + c1]) : -1e30f;

        float m = fmaxf(lg0, lg1);
#pragma unroll
        for (int s = 16; s > 0; s >>= 1)
            m = fmaxf(m, __shfl_xor_sync(0xffffffffu, m, s));
        float e0 = __expf(lg0 - m);
        float e1 = l2 ? __expf(lg1 - m) : 0.f;
        float sum = e0 + e1;
#pragma unroll
        for (int s = 16; s > 0; s >>= 1)
            sum += __shfl_xor_sync(0xffffffffu, sum, s);
        float inv = 1.0f / sum;

        float* wslot = &pw[pix * 52];
        wslot[lane] = e0;
        if (l2) wslot[32 + lane] = e1;
        __syncwarp();

        float acc = 0.f;
#pragma unroll
        for (int a = 0; a < 7; a++) {
            const float* vrow = &vs[((si + a - rstart) * 14 + (sj - cstart)) * 33 + lane];
#pragma unroll
            for (int c = 0; c < 7; c++)
                acc = fmaf(wslot[a * 7 + c], vrow[c * 33], acc);
        }
        __syncwarp();

        size_t pg = (size_t)bb * HWW + (size_t)i * WW + j;
        g_ao[pg * CC + head * DH + lane] = to_tf32(acc * inv);
    }
}

// ---------------------------------------------------------------------------
// Kernel 3: proj GEMM (tf32, cp.async double-buffered) + bias + NCHW store.
// Reads g_ao / g_wp via device-side symbol reference.
// BM=64, BN=256, BK=32, warp tile 64x32. As: [m][k] stride 36; Bs: [n][k] 36.
// ---------------------------------------------------------------------------
__global__ __launch_bounds__(256, 2)
void proj_gemm_tc(const float* __restrict__ bias, float* __restrict__ y)
{
    extern __shared__ float dsm[];
    const float* __restrict__ w = g_wp;

    int m0 = blockIdx.x * 64;
    int n0 = blockIdx.y * 256;
    int b  = m0 / HWW;
    int pb0 = m0 % HWW;
    int t = threadIdx.x;
    int warp = t >> 5, lane = t & 31;
    int tg = lane & 3, g = lane >> 2;

    float c[4][4][4];
#pragma unroll
    for (int mt = 0; mt < 4; mt++)
#pragma unroll
        for (int nt = 0; nt < 4; nt++)
#pragma unroll
            for (int r = 0; r < 4; r++) c[mt][nt][r] = 0.f;

    const float* A = g_ao + (size_t)m0 * CC;

    auto issue_tile = [&](int k0, float* buf) {
        float* As = buf;
        float* Bs = buf + 2304;
#pragma unroll
        for (int p = 0; p < 2; p++) {
            int idx = t + 256 * p;
            int mm = idx >> 3, k4 = (idx & 7) * 4;
            cp_async16(&As[mm * 36 + k4], A + (size_t)mm * CC + k0 + k4);
        }
#pragma unroll
        for (int i = 0; i < 8; i++) {
            int idx = t + 256 * i;
            int nn = idx >> 3, k4 = (idx & 7) * 4;
            cp_async16(&Bs[nn * 36 + k4], w + (size_t)(n0 + nn) * CC + k0 + k4);
        }
    };

    issue_tile(0, dsm);
    CP_COMMIT();

    for (int it = 0; it < 16; it++) {
        float* As = dsm + (it & 1) * SBUF;
        float* Bs = As + 2304;

        CP_WAIT0();
        __syncthreads();
        if (it < 15) {
            issue_tile((it + 1) * 32, dsm + ((it + 1) & 1) * SBUF);
            CP_COMMIT();
        }

#pragma unroll
        for (int ks = 0; ks < 4; ks++) {
            int kb = ks * 8;
            uint32_t a[4][4];
#pragma unroll
            for (int mt = 0; mt < 4; mt++) {
                int mb = mt * 16 + g;
                a[mt][0] = __float_as_uint(As[mb * 36 + kb + tg]);
                a[mt][1] = __float_as_uint(As[(mb + 8) * 36 + kb + tg]);
                a[mt][2] = __float_as_uint(As[mb * 36 + kb + tg + 4]);
                a[mt][3] = __float_as_uint(As[(mb + 8) * 36 + kb + tg + 4]);
            }
            uint32_t bq[4][2];
#pragma unroll
            for (int nt = 0; nt < 4; nt++) {
                int nn = warp * 32 + nt * 8 + g;
                bq[nt][0] = __float_as_uint(Bs[nn * 36 + kb + tg]);
                bq[nt][1] = __float_as_uint(Bs[nn * 36 + kb + tg + 4]);
            }
#pragma unroll
            for (int mt = 0; mt < 4; mt++)
#pragma unroll
                for (int nt = 0; nt < 4; nt++)
                    mma_tf32(c[mt][nt], a[mt][0], a[mt][1], a[mt][2], a[mt][3],
                             bq[nt][0], bq[nt][1]);
        }
        __syncthreads();
    }

    // ---- epilogue: NCHW store with bias ----
#pragma unroll
    for (int nt = 0; nt < 4; nt++) {
        int n = n0 + warp * 32 + nt * 8 + 2 * tg;
        float bv0 = bias[n];
        float bv1 = bias[n + 1];
        float* y0 = y + ((size_t)b * CC + n) * HWW;
        float* y1 = y0 + HWW;
#pragma unroll
        for (int mt = 0; mt < 4; mt++) {
#pragma unroll
            for (int h = 0; h < 2; h++) {
                int hw = pb0 + mt * 16 + g + h * 8;
                y0[hw] = c[mt][nt][h * 2]     + bv0;
                y1[hw] = c[mt][nt][h * 2 + 1] + bv1;
            }
        }
    }
}

// ---------------------------------------------------------------------------
extern "C" void kernel_launch(void* const* d_in, const int* in_sizes, int n_in,
                              void* d_out, int out_size)
{
    const float* x      = (const float*)d_in[0];
    const float* qkv_w  = (const float*)d_in[1];
    const float* rpb    = (const float*)d_in[2];
    const float* proj_w = (const float*)d_in[3];
    const float* proj_b = (const float*)d_in[4];
    float* y = (float*)d_out;

    cudaFuncSetAttribute(qkv_gemm_tc,
        cudaFuncAttributeMaxDynamicSharedMemorySize, SMEM_GEMM_BYTES);
    cudaFuncSetAttribute(proj_gemm_tc,
        cudaFuncAttributeMaxDynamicSharedMemorySize, SMEM_GEMM_BYTES);

    prep_round <<<2048, 256>>>(x, qkv_w, proj_w);
    qkv_gemm_tc<<<dim3(392, 6), 256, SMEM_GEMM_BYTES>>>();
    attn_kernel<<<dim3(7, 14, NB * NHEADS), 256>>>(rpb);
    proj_gemm_tc<<<dim3(392, 2), 256, SMEM_GEMM_BYTES>>>(proj_b, y);
}